// round 10
// baseline (speedup 1.0000x reference)
#include <cuda_runtime.h>
#include <math.h>

#define BATCH    64
#define DIN      1024
#define DOUT     1024
#define ISPLITS  37                  // grid = 37*8 = 296 = 2 CTAs per SM (148 SMs)
#define CHUNK_HI 28                  // first 25 chunks: 28 rows
#define CHUNK_LO 27                  // last 12 chunks: 27 rows (25*28+12*27 = 1024)
#define N_HI     25
#define BTILE    8
#define BTILES   (BATCH / BTILE)     // 8
#define THREADS  256                 // 256 threads * float4 = 1024 = DOUT
#define O4S      (DOUT / 4)          // 256 float4s along o

// Scratch (static __device__ globals — allocation-free per harness rules)
__device__ float        g_part[ISPLITS * BATCH * DOUT];  // 9.7 MB i-split partials
__device__ unsigned int g_cnt[BTILES];                   // zero-init; self-resetting

// Fast softplus: max(v,0) + log1p(exp(-|v|)) with MUFU intrinsics.
__device__ __forceinline__ float softplus_fast(float v) {
    float e = __expf(-fabsf(v));
    return fmaxf(v, 0.0f) + __logf(1.0f + e);
}

// ---------------------------------------------------------------------------
// Single fused kernel.
// Phase 1: grid = (ISPLITS, BTILES) = (37, 8) = 296 CTAs (2/SM, balanced).
//   Each CTA: 8 batches x {27|28} i-rows x all 1024 o, inline softplus,
//   eps loaded evict-first (touched once chip-wide). Partials -> g_part.
// Phase 2 (last-CTA-done per b-tile): the 37th CTA to finish a b-tile sums
//   the 37 partials (fixed s-order -> deterministic), adds bias, writes out.
//   Partials are L2-hot (just written) and the work overlaps other b-tiles'
//   stragglers — no second kernel launch.
// ---------------------------------------------------------------------------
__global__ __launch_bounds__(THREADS) void fused_kernel(
    const float* __restrict__ x,
    const float* __restrict__ mu,
    const float* __restrict__ ro,
    const float* __restrict__ eps,
    const float* __restrict__ mu_bias,
    const float* __restrict__ ro_bias,
    const float* __restrict__ eps_bias,
    float* __restrict__ out)
{
    const int ic  = blockIdx.x;          // i-chunk: 0..36
    const int bt  = blockIdx.y;          // b-tile:  0..7
    const int len = (ic < N_HI) ? CHUNK_HI : CHUNK_LO;
    const int i0  = (ic < N_HI) ? ic * CHUNK_HI
                                : N_HI * CHUNK_HI + (ic - N_HI) * CHUNK_LO;
    const int b0  = bt * BTILE;
    const int o4  = threadIdx.x;         // float4 index along o

    __shared__ float sx[BTILE][CHUNK_HI];   // 8 x 28 max
    {
        const int t = threadIdx.x;
        if (t < BTILE * len) {              // <= 224 < 256
            const int bb = t / len;
            const int ii = t % len;
            sx[bb][ii] = x[(b0 + bb) * DIN + i0 + ii];
        }
    }
    __syncthreads();

    float4 acc[BTILE];
#pragma unroll
    for (int bb = 0; bb < BTILE; bb++) acc[bb] = make_float4(0.f, 0.f, 0.f, 0.f);

    const float4* ro4  = reinterpret_cast<const float4*>(ro);
    const float4* mu4  = reinterpret_cast<const float4*>(mu);
    const float4* eps4 = reinterpret_cast<const float4*>(eps);

    int row   = i0 * O4S + o4;               // ro/mu float4 index
    int ebase = (b0 * DIN + i0) * O4S + o4;  // eps float4 index (<= 16.7M)

#pragma unroll 4
    for (int ii = 0; ii < len; ii++) {
        const float4 r = ro4[row];
        const float4 m = mu4[row];
        float4 sg;
        sg.x = softplus_fast(r.x);
        sg.y = softplus_fast(r.y);
        sg.z = softplus_fast(r.z);
        sg.w = softplus_fast(r.w);
#pragma unroll
        for (int bb = 0; bb < BTILE; bb++) {
            const float  xv = sx[bb][ii];
            const float4 e  = __ldcs(&eps4[ebase + bb * (DIN * O4S)]);
            acc[bb].x = fmaf(xv, fmaf(e.x, sg.x, m.x), acc[bb].x);
            acc[bb].y = fmaf(xv, fmaf(e.y, sg.y, m.y), acc[bb].y);
            acc[bb].z = fmaf(xv, fmaf(e.z, sg.z, m.z), acc[bb].z);
            acc[bb].w = fmaf(xv, fmaf(e.w, sg.w, m.w), acc[bb].w);
        }
        row   += O4S;
        ebase += O4S;
    }

    // Store partials (default policy — L2-hot for the imminent reduce).
    float4* p4 = reinterpret_cast<float4*>(g_part);
#pragma unroll
    for (int bb = 0; bb < BTILE; bb++) {
        p4[(ic * BATCH + b0 + bb) * O4S + o4] = acc[bb];
    }

    // ---- last-CTA-done reduction for this b-tile ----
    __threadfence();                          // release partial stores
    __shared__ unsigned int s_rank;
    if (threadIdx.x == 0)
        s_rank = atomicAdd(&g_cnt[bt], 1u);
    __syncthreads();

    if (s_rank == ISPLITS - 1) {
        __threadfence();                      // acquire other CTAs' partials

        const float4* pc = reinterpret_cast<const float4*>(g_part);
        // 8 b x 256 o4 = 2048 outputs; 256 threads -> 8 outputs each.
#pragma unroll
        for (int rIdx = 0; rIdx < BTILE; rIdx++) {
            const int local = rIdx * THREADS + threadIdx.x;  // 0..2047
            const int bb    = local >> 8;                    // /O4S
            const int oo    = local & (O4S - 1);
            const int g4    = (b0 + bb) * O4S + oo;

            float4 sum = make_float4(0.f, 0.f, 0.f, 0.f);
            const int base = (b0 + bb) * O4S + oo;
#pragma unroll 4
            for (int s = 0; s < ISPLITS; s++) {              // fixed order: deterministic
                const float4 p = pc[s * (BATCH * O4S) + base];
                sum.x += p.x; sum.y += p.y; sum.z += p.z; sum.w += p.w;
            }

            const float4 rb = reinterpret_cast<const float4*>(ro_bias)[oo];
            const float4 mb = reinterpret_cast<const float4*>(mu_bias)[oo];
            const float4 eb = reinterpret_cast<const float4*>(eps_bias)[g4];

            float4 res;
            res.x = sum.x + fmaf(eb.x, softplus_fast(rb.x), mb.x);
            res.y = sum.y + fmaf(eb.y, softplus_fast(rb.y), mb.y);
            res.z = sum.z + fmaf(eb.z, softplus_fast(rb.z), mb.z);
            res.w = sum.w + fmaf(eb.w, softplus_fast(rb.w), mb.w);
            reinterpret_cast<float4*>(out)[g4] = res;
        }

        __syncthreads();                      // all reduce loads done
        if (threadIdx.x == 0)
            g_cnt[bt] = 0;                    // reset: graph-replay safe
    }
}

// ---------------------------------------------------------------------------
// Launch. Inputs (metadata order): x, mu, ro, mu_bias, ro_bias, eps, eps_bias
// ---------------------------------------------------------------------------
extern "C" void kernel_launch(void* const* d_in, const int* in_sizes, int n_in,
                              void* d_out, int out_size) {
    const float* x        = (const float*)d_in[0];
    const float* mu       = (const float*)d_in[1];
    const float* ro       = (const float*)d_in[2];
    const float* mu_bias  = (const float*)d_in[3];
    const float* ro_bias  = (const float*)d_in[4];
    const float* eps      = (const float*)d_in[5];
    const float* eps_bias = (const float*)d_in[6];
    float* out = (float*)d_out;

    dim3 grid(ISPLITS, BTILES);
    fused_kernel<<<grid, THREADS>>>(x, mu, ro, eps,
                                    mu_bias, ro_bias, eps_bias, out);
}